// round 8
// baseline (speedup 1.0000x reference)
#include <cuda_runtime.h>

// Problem shapes (fixed by dataset)
#define BATCH 128
#define CHAN  2048
#define PP    14          // spatial extent
#define HW    196         // 14*14
#define NBOX  36
#define CC    64          // channels per block
#define NTHREADS 1024
#define TILE_PAD 197      // odd stride: c-strided att reads conflict-free
#define RW    15          // row-prefix width (P+1): R[y][x] = sum of row y cols < x
#define RSZ   225         // 15*15 channel stride, 225 % 32 == 1 -> conflict-free
#define SMEM_BYTES ((CC*TILE_PAD + CC*RSZ) * sizeof(float))  // 108,032 B -> 2 CTAs/SM, 100% occ

// XOR component swizzle: element (c, hw) stored at c*TILE_PAD + swzpos(hw).
// Stride-4 scalar STS hits all 32 banks; odd-stride att gather conflict-free.
__device__ __forceinline__ int swzpos(int hw) {
    int q = hw >> 2;
    return 4 * q + ((hw & 3) ^ ((q >> 3) & 3));
}

__device__ __forceinline__ void stcs4(float* p, float4 v) {
#if __CUDA_ARCH__ >= 800
    __stcs((float4*)p, v);
#else
    *(float4*)p = v;
#endif
}

__global__ __launch_bounds__(NTHREADS, 2)
void fused_pool_transpose_region(
    const float* __restrict__ images,   // [B, C, 14, 14]
    const float* __restrict__ boxes,    // [B, 36, 4]
    float* __restrict__ fc,             // [B, C]
    float* __restrict__ att,            // [B, 196, C]
    float* __restrict__ bu)             // [B, 36, C]
{
    extern __shared__ float smem[];
    float* tile = smem;                 // [CC][TILE_PAD], XOR-swizzled components
    float* rpf  = smem + CC * TILE_PAD; // [CC][RSZ]  rpf[c][y*15+x] = row-prefix

    __shared__ int   bx1[NBOX], by1[NBOX], bx2[NBOX], by2[NBOX];
    __shared__ float barea[NBOX];

    const int b   = blockIdx.y;
    const int c0  = blockIdx.x * CC;
    const int tid = threadIdx.x;

    const float* img = images + ((size_t)b * CHAN + c0) * HW;

    // ---- box coordinates (replicates reference rounding/degenerate fix) ----
    if (tid < NBOX) {
        const float* bp = boxes + ((size_t)b * NBOX + tid) * 4;
        int x1 = (int)rintf(bp[0] * (float)PP);   // round-half-even == jnp.round
        int y1 = (int)rintf(bp[1] * (float)PP);
        int x2 = (int)rintf(bp[2] * (float)PP);
        int y2 = (int)rintf(bp[3] * (float)PP);
        bool eqx = (x1 == x2);
        if (eqx && x2 <  PP) x2 += 1;
        if (eqx && x2 >= PP && x1 > 0 && x1 == x2) x1 -= 1;
        bool eqy = (y1 == y2);
        if (eqy && y2 <  PP) y2 += 1;
        if (eqy && y2 >= PP && y1 > 0 && y1 == y2) y1 -= 1;
        bx1[tid] = x1; by1[tid] = y1; bx2[tid] = x2; by2[tid] = y2;
        barea[tid] = (float)((y2 - y1) * (x2 - x1));
    }

    // ---- load tile: LDG.128 stream, swizzled conflict-free scalar STS ----
    {
        const float4* img4 = (const float4*)img;
        #pragma unroll
        for (int i = tid; i < CC * 49; i += NTHREADS) {
            float4 v = img4[i];
            int c = i / 49, q = i - c * 49;
            float* d = tile + c * TILE_PAD + 4 * q;
            int k = (q >> 3) & 3;
            d[0 ^ k] = v.x; d[1 ^ k] = v.y; d[2 ^ k] = v.z; d[3 ^ k] = v.w;
        }
    }
    __syncthreads();

    // ---- att: transpose, two 32-channel halves; within-warp pattern
    //      (8 c-groups x 4 hw) is conflict-free, stores STG.128 streaming ----
    {
        float* attb = att + (size_t)b * HW * CHAN + c0;
        #pragma unroll
        for (int h = 0; h < 2; h++) {
            const float* th = tile + 32 * h * TILE_PAD;
            float*       ah = attb + 32 * h;
            #pragma unroll
            for (int i = tid; i < HW * 8; i += NTHREADS) {   // 1568 groups
                int c4 = i & 7;          // 8 groups of 4 channels, c4 fastest
                int hw = i >> 3;
                int p  = swzpos(hw);
                float4 v;
                v.x = th[(4 * c4 + 0) * TILE_PAD + p];
                v.y = th[(4 * c4 + 1) * TILE_PAD + p];
                v.z = th[(4 * c4 + 2) * TILE_PAD + p];
                v.w = th[(4 * c4 + 3) * TILE_PAD + p];
                stcs4(ah + (size_t)hw * CHAN + 4 * c4, v);
            }
        }
    }

    // ---- row prefix only: thread per (c, y), 896 threads active ----
    if (tid < CC * PP) {
        int c = tid / PP, y = tid - c * PP;
        const float* tc  = tile + c * TILE_PAD;
        float*       dst = rpf  + c * RSZ + y * RW;
        dst[0] = 0.0f;
        float acc = 0.0f;
        #pragma unroll
        for (int x = 0; x < PP; x++) { acc += tc[swzpos(y * PP + x)]; dst[x + 1] = acc; }
    }
    __syncthreads();

    // ---- fc: column-sum of full row sums / 196 (two warps, lanes = c) ----
    if (tid < CC) {
        const float* Rc = rpf + tid * RSZ;
        float s = 0.0f;
        #pragma unroll
        for (int y = 0; y < PP; y++) s += Rc[y * RW + PP];
        fc[(size_t)b * CHAN + c0 + tid] = s * (1.0f / (float)HW);
    }

    // ---- bu: vertical accumulation of row-prefix diffs; lane = c (conflict-
    //      free, c mod 32 distinct), warp-uniform y trip count ----
    {
        float* bub = bu + (size_t)b * NBOX * CHAN + c0;
        for (int i = tid; i < NBOX * CC; i += NTHREADS) {
            int r = i >> 6, c = i & 63;
            const float* Rc = rpf + c * RSZ;
            int x1 = bx1[r], y1 = by1[r], x2 = bx2[r], y2 = by2[r];
            float s = 0.0f;
            for (int y = y1; y < y2; y++)
                s += Rc[y * RW + x2] - Rc[y * RW + x1];
            bub[(size_t)r * CHAN + c] = s / barea[r];
        }
    }
}

extern "C" void kernel_launch(void* const* d_in, const int* in_sizes, int n_in,
                              void* d_out, int out_size)
{
    const float* images = (const float*)d_in[0];
    const float* boxes  = (const float*)d_in[1];

    float* out = (float*)d_out;
    float* fc  = out;                                   // [128, 2048]
    float* att = fc  + (size_t)BATCH * CHAN;            // [128, 196, 2048]
    float* bu  = att + (size_t)BATCH * HW * CHAN;       // [128, 36, 2048]

    cudaFuncSetAttribute(fused_pool_transpose_region,
                         cudaFuncAttributeMaxDynamicSharedMemorySize,
                         (int)SMEM_BYTES);

    dim3 grid(CHAN / CC, BATCH);
    fused_pool_transpose_region<<<grid, NTHREADS, SMEM_BYTES>>>(
        images, boxes, fc, att, bu);
}

// round 9
// speedup vs baseline: 1.6027x; 1.6027x over previous
#include <cuda_runtime.h>

// Problem shapes (fixed by dataset)
#define BATCH 128
#define CHAN  2048
#define PP    14          // spatial extent
#define HW    196         // 14*14
#define NBOX  36
#define CC    32          // channels per block
#define NTHREADS 512
#define TILE_PAD 197      // odd stride: c-strided att reads conflict-free
#define RW    15          // row-prefix width (P+1): R[y][x] = sum of row y cols < x
#define RSZ   225         // 15*15 channel stride, 225 % 32 == 1 -> conflict-free
#define SMEM_BYTES ((CC*TILE_PAD + CC*RSZ) * sizeof(float))  // 54,016 B -> 4 CTAs/SM

// XOR component swizzle: element (c, hw) stored at c*TILE_PAD + swzpos(hw).
// Stride-4 scalar STS hits all 32 banks; odd-stride att gather conflict-free.
__device__ __forceinline__ int swzpos(int hw) {
    int q = hw >> 2;
    return 4 * q + ((hw & 3) ^ ((q >> 3) & 3));
}

__global__ __launch_bounds__(NTHREADS, 4)
void fused_pool_transpose_region(
    const float* __restrict__ images,   // [B, C, 14, 14]
    const float* __restrict__ boxes,    // [B, 36, 4]
    float* __restrict__ fc,             // [B, C]
    float* __restrict__ att,            // [B, 196, C]
    float* __restrict__ bu)             // [B, 36, C]
{
    extern __shared__ float smem[];
    float* tile = smem;                 // [CC][TILE_PAD], XOR-swizzled components
    float* rpf  = smem + CC * TILE_PAD; // [CC][RSZ]  rpf[c][y*15+x] = row-prefix

    __shared__ int   bx1[NBOX], by1[NBOX], bx2[NBOX], by2[NBOX];
    __shared__ float barea[NBOX];

    const int b   = blockIdx.y;
    const int c0  = blockIdx.x * CC;
    const int tid = threadIdx.x;

    const float* img = images + ((size_t)b * CHAN + c0) * HW;

    // ---- box coordinates (replicates reference rounding/degenerate fix) ----
    if (tid < NBOX) {
        const float* bp = boxes + ((size_t)b * NBOX + tid) * 4;
        int x1 = (int)rintf(bp[0] * (float)PP);   // round-half-even == jnp.round
        int y1 = (int)rintf(bp[1] * (float)PP);
        int x2 = (int)rintf(bp[2] * (float)PP);
        int y2 = (int)rintf(bp[3] * (float)PP);
        bool eqx = (x1 == x2);
        if (eqx && x2 <  PP) x2 += 1;
        if (eqx && x2 >= PP && x1 > 0 && x1 == x2) x1 -= 1;
        bool eqy = (y1 == y2);
        if (eqy && y2 <  PP) y2 += 1;
        if (eqy && y2 >= PP && y1 > 0 && y1 == y2) y1 -= 1;
        bx1[tid] = x1; by1[tid] = y1; bx2[tid] = x2; by2[tid] = y2;
        barea[tid] = (float)((y2 - y1) * (x2 - x1));
    }

    // ---- load tile: LDG.128 stream, swizzled conflict-free scalar STS ----
    {
        const float4* img4 = (const float4*)img;
        #pragma unroll
        for (int i = tid; i < CC * 49; i += NTHREADS) {
            float4 v = img4[i];
            int c = i / 49, q = i - c * 49;
            float* d = tile + c * TILE_PAD + 4 * q;
            int k = (q >> 3) & 3;
            d[0 ^ k] = v.x; d[1 ^ k] = v.y; d[2 ^ k] = v.z; d[3 ^ k] = v.w;
        }
    }
    __syncthreads();

    // ---- att: transpose, strength-reduced; identical mapping to before:
    //      c4 = tid&7 (invariant since 512 % 8 == 0), hw strided by 64.
    //      4 conflict-free swizzled LDS -> 1 STG.128 per iter. ----
    {
        const int c4  = tid & 7;
        const int hw0 = tid >> 3;                  // 0..63
        const float* t0 = tile + (4 * c4 + 0) * TILE_PAD;
        const float* t1 = tile + (4 * c4 + 1) * TILE_PAD;
        const float* t2 = tile + (4 * c4 + 2) * TILE_PAD;
        const float* t3 = tile + (4 * c4 + 3) * TILE_PAD;
        float* a = att + (size_t)b * HW * CHAN + c0 + (size_t)hw0 * CHAN + 4 * c4;
        #pragma unroll
        for (int hw = hw0; hw < HW; hw += 64, a += 64 * CHAN) {
            int p = swzpos(hw);
            float4 v;
            v.x = t0[p]; v.y = t1[p]; v.z = t2[p]; v.w = t3[p];
            *(float4*)a = v;
        }
    }

    // ---- row prefix only: thread per (c, y), 448 threads active ----
    if (tid < CC * PP) {
        int c = tid / PP, y = tid - c * PP;
        const float* tc  = tile + c * TILE_PAD;
        float*       dst = rpf  + c * RSZ + y * RW;
        dst[0] = 0.0f;
        float acc = 0.0f;
        #pragma unroll
        for (int x = 0; x < PP; x++) { acc += tc[swzpos(y * PP + x)]; dst[x + 1] = acc; }
    }
    __syncthreads();

    // ---- fc: column-sum of full row sums / 196 (one warp, lanes = c) ----
    if (tid < CC) {
        const float* Rc = rpf + tid * RSZ;
        float s = 0.0f;
        #pragma unroll
        for (int y = 0; y < PP; y++) s += Rc[y * RW + PP];
        fc[(size_t)b * CHAN + c0 + tid] = s * (1.0f / (float)HW);
    }

    // ---- bu: vertical accumulation of row-prefix diffs; warp = box, lane = c
    //      -> uniform trip count per warp, conflict-free lane-strided LDS ----
    {
        float* bub = bu + (size_t)b * NBOX * CHAN + c0;
        for (int i = tid; i < NBOX * CC; i += NTHREADS) {
            int r = i >> 5, c = i & 31;
            const float* Rc = rpf + c * RSZ;
            int x1 = bx1[r], y1 = by1[r], x2 = bx2[r], y2 = by2[r];
            float s = 0.0f;
            for (int y = y1; y < y2; y++)
                s += Rc[y * RW + x2] - Rc[y * RW + x1];
            bub[(size_t)r * CHAN + c] = s / barea[r];
        }
    }
}

extern "C" void kernel_launch(void* const* d_in, const int* in_sizes, int n_in,
                              void* d_out, int out_size)
{
    const float* images = (const float*)d_in[0];
    const float* boxes  = (const float*)d_in[1];

    float* out = (float*)d_out;
    float* fc  = out;                                   // [128, 2048]
    float* att = fc  + (size_t)BATCH * CHAN;            // [128, 196, 2048]
    float* bu  = att + (size_t)BATCH * HW * CHAN;       // [128, 36, 2048]

    cudaFuncSetAttribute(fused_pool_transpose_region,
                         cudaFuncAttributeMaxDynamicSharedMemorySize,
                         (int)SMEM_BYTES);

    dim3 grid(CHAN / CC, BATCH);
    fused_pool_transpose_region<<<grid, NTHREADS, SMEM_BYTES>>>(
        images, boxes, fc, att, bu);
}